// round 12
// baseline (speedup 1.0000x reference)
#include <cuda_runtime.h>

typedef unsigned long long ull;

#define Bsz   512
#define Hh    1024
#define INd   128
#define OUTROW 10240   // 80*128, per-batch row stride of output

// ------------------------- persistent device scratch -----------------------
__device__ float g_h0[2][Bsz * Hh];
__device__ float g_h1[2][Bsz * Hh];
__device__ float g_c0[Bsz * Hh];
__device__ float g_c1[Bsz * Hh];
__device__ float g_xlast[Bsz * INd];
__device__ float g_pp[8 * Bsz * INd];   // proj split-K partials

// ------------------------------ f32x2 helpers ------------------------------
__device__ __forceinline__ ull dup2(float x) {
    unsigned xi = __float_as_uint(x);
    ull r;
    asm("mov.b64 %0, {%1, %1};" : "=l"(r) : "r"(xi));
    return r;
}
__device__ __forceinline__ void ffma2(ull& c, ull a, ull b) {
    asm("fma.rn.f32x2 %0, %1, %2, %0;" : "+l"(c) : "l"(a), "l"(b));
}
__device__ __forceinline__ void unpk(ull v, float& lo, float& hi) {
    unsigned a, b;
    asm("mov.b64 {%0, %1}, %2;" : "=r"(a), "=r"(b) : "l"(v));
    lo = __uint_as_float(a);
    hi = __uint_as_float(b);
}
__device__ __forceinline__ float sigf(float x) {
    return 1.0f / (1.0f + expf(-x));
}

// ------------------------------ init kernels --------------------------------
__global__ void zero_state_kernel() {
    int idx = blockIdx.x * 256 + threadIdx.x;
    if (idx < Bsz * Hh) {
        g_c0[idx] = 0.f; g_c1[idx] = 0.f;
        g_h0[0][idx] = 0.f; g_h0[1][idx] = 0.f;
        g_h1[0][idx] = 0.f; g_h1[1][idx] = 0.f;
    }
}

__global__ void copy_prompt_kernel(const float* __restrict__ x,
                                   float* __restrict__ out) {
    int idx = blockIdx.x * 256 + threadIdx.x;   // < 512*16*128
    int b = idx >> 11;
    int rem = idx & 2047;
    out[(size_t)b * OUTROW + rem] = x[idx];
}

// ------------------------------ LSTM cell kernel ----------------------------
// G[b, g*H+j] = A[b,:]·Wih[g*H+j,:] + Hprev[b,:]·Whh[g*H+j,:] + bih + bhh
// then c = sig(f)*c + sig(i)*tanh(g); hNext = sig(o)*tanh(c)
// CTA tile: 128 b x (32 j x 4 gates); SMEM N-col = jj*4 + gate.
// xsel: 0 = Xext, 1 = g_xlast, 2 = g_h0[wr] (layer1 input)
__global__ void __launch_bounds__(256, 1)
lstm_cell_kernel(const float* __restrict__ Xext, int ldX, int Kx,
                 const float* __restrict__ Wih,
                 const float* __restrict__ Whh,
                 const float* __restrict__ bih,
                 const float* __restrict__ bhh,
                 int layer, int rd, int wr, int xsel)
{
    __shared__ __align__(16) float Xs[16][132];
    __shared__ __align__(16) float Ws[16][132];

    const float* X = (xsel == 0) ? Xext : (xsel == 1 ? g_xlast : g_h0[wr]);
    const float* Hprev = layer ? g_h1[rd] : g_h0[rd];
    float* Hnext = layer ? g_h1[wr] : g_h0[wr];
    float* Cst   = layer ? g_c1 : g_c0;

    const int tid   = threadIdx.x;
    const int jBase = blockIdx.x << 5;   // 32 j per CTA
    const int bBase = blockIdx.y << 7;   // 128 b per CTA
    const int lr = tid >> 2;             // loader row 0..63
    const int lk = (tid & 3) << 2;       // loader k offset 0,4,8,12
    const int ty = tid >> 4;             // 0..15 -> 8 b rows
    const int tx = tid & 15;             // 0..15 -> 8 n cols (2 j x 4 gates)

    ull acc[8][4];
#pragma unroll
    for (int r = 0; r < 8; ++r)
#pragma unroll
        for (int p = 0; p < 4; ++p) acc[r][p] = 0ull;

    const int r0 = lr, r1 = lr + 64;
    const int c0 = ((r0 & 31) << 2) + (r0 >> 5);
    const int c1 = ((r1 & 31) << 2) + (r1 >> 5);

#pragma unroll 1
    for (int phase = 0; phase < 2; ++phase) {
        const float* A  = phase ? Hprev : X;
        const int   ldA = phase ? Hh : ldX;
        const float* W  = phase ? Whh : Wih;
        const int   ldW = phase ? Hh : Kx;
        const int   Ks  = phase ? Hh : Kx;

        const size_t aOff0 = (size_t)(bBase + r0) * ldA + lk;
        const size_t aOff1 = (size_t)(bBase + r1) * ldA + lk;
        const size_t wOff0 = (size_t)(((r0 >> 5) << 10) + jBase + (r0 & 31)) * ldW + lk;
        const size_t wOff1 = (size_t)(((r1 >> 5) << 10) + jBase + (r1 & 31)) * ldW + lk;

        float4 pa0 = *(const float4*)(A + aOff0);
        float4 pa1 = *(const float4*)(A + aOff1);
        float4 pw0 = *(const float4*)(W + wOff0);
        float4 pw1 = *(const float4*)(W + wOff1);

#pragma unroll 1
        for (int k0 = 0; k0 < Ks; k0 += 16) {
            __syncthreads();
            Xs[lk + 0][r0] = pa0.x; Xs[lk + 1][r0] = pa0.y;
            Xs[lk + 2][r0] = pa0.z; Xs[lk + 3][r0] = pa0.w;
            Xs[lk + 0][r1] = pa1.x; Xs[lk + 1][r1] = pa1.y;
            Xs[lk + 2][r1] = pa1.z; Xs[lk + 3][r1] = pa1.w;
            Ws[lk + 0][c0] = pw0.x; Ws[lk + 1][c0] = pw0.y;
            Ws[lk + 2][c0] = pw0.z; Ws[lk + 3][c0] = pw0.w;
            Ws[lk + 0][c1] = pw1.x; Ws[lk + 1][c1] = pw1.y;
            Ws[lk + 2][c1] = pw1.z; Ws[lk + 3][c1] = pw1.w;
            __syncthreads();

            if (k0 + 16 < Ks) {
                pa0 = *(const float4*)(A + aOff0 + k0 + 16);
                pa1 = *(const float4*)(A + aOff1 + k0 + 16);
                pw0 = *(const float4*)(W + wOff0 + k0 + 16);
                pw1 = *(const float4*)(W + wOff1 + k0 + 16);
            }

#pragma unroll
            for (int kk = 0; kk < 16; ++kk) {
                float4 a0 = *(const float4*)&Xs[kk][ty << 3];
                float4 a1 = *(const float4*)&Xs[kk][(ty << 3) + 4];
                ull b0 = *(const ull*)&Ws[kk][(tx << 3) + 0];
                ull b1 = *(const ull*)&Ws[kk][(tx << 3) + 2];
                ull b2 = *(const ull*)&Ws[kk][(tx << 3) + 4];
                ull b3 = *(const ull*)&Ws[kk][(tx << 3) + 6];
                float av[8] = {a0.x, a0.y, a0.z, a0.w, a1.x, a1.y, a1.z, a1.w};
#pragma unroll
                for (int r = 0; r < 8; ++r) {
                    ull ad = dup2(av[r]);
                    ffma2(acc[r][0], ad, b0);
                    ffma2(acc[r][1], ad, b1);
                    ffma2(acc[r][2], ad, b2);
                    ffma2(acc[r][3], ad, b3);
                }
            }
        }
    }

    // fused LSTM epilogue: gates (i,f,g,o) per (b,j) live in registers
    const int jcol = jBase + (tx << 1);
    float bi[2][4];
#pragma unroll
    for (int q = 0; q < 2; ++q)
#pragma unroll
        for (int g = 0; g < 4; ++g) {
            const int gi = (g << 10) + jcol + q;
            bi[q][g] = bih[gi] + bhh[gi];
        }
#pragma unroll
    for (int r = 0; r < 8; ++r) {
        const int b = bBase + (ty << 3) + r;
#pragma unroll
        for (int q = 0; q < 2; ++q) {
            float iv, fv, gv, ov;
            unpk(acc[r][(q << 1) + 0], iv, fv);
            unpk(acc[r][(q << 1) + 1], gv, ov);
            iv += bi[q][0]; fv += bi[q][1];
            gv += bi[q][2]; ov += bi[q][3];
            const size_t idx = (size_t)b * Hh + jcol + q;
            const float cNew = sigf(fv) * Cst[idx] + sigf(iv) * tanhf(gv);
            Cst[idx]   = cNew;
            Hnext[idx] = sigf(ov) * tanhf(cNew);
        }
    }
}

// --------------------- output projection: split-K partials ------------------
// PP[ks, b, i] = sum_{k in 128-wide chunk ks} h1[b,k] * Wout[i,k]
__global__ void __launch_bounds__(256, 1)
proj_part_kernel(const float* __restrict__ Wout, int wr)
{
    __shared__ __align__(16) float Hs[16][68];
    __shared__ __align__(16) float Ws2[16][132];

    const float* H1 = g_h1[wr];
    const int tid   = threadIdx.x;
    const int ks    = blockIdx.x;        // 0..7 K split
    const int bBase = blockIdx.y << 6;   // 64 b per CTA
    const int k0    = ks << 7;
    const int lr = tid >> 2;             // 0..63
    const int lk = (tid & 3) << 2;
    const int ty = tid >> 5;             // 0..7 -> 8 b rows
    const int tx = tid & 31;             // 0..31 -> 4 i cols

    ull acc[8][2];
#pragma unroll
    for (int r = 0; r < 8; ++r) { acc[r][0] = 0ull; acc[r][1] = 0ull; }

    const size_t hOff  = (size_t)(bBase + lr) * Hh + k0 + lk;
    const size_t wOff0 = (size_t)lr * Hh + k0 + lk;
    const size_t wOff1 = (size_t)(lr + 64) * Hh + k0 + lk;

    float4 ph  = *(const float4*)(H1 + hOff);
    float4 pw0 = *(const float4*)(Wout + wOff0);
    float4 pw1 = *(const float4*)(Wout + wOff1);

#pragma unroll 1
    for (int kb = 0; kb < 8; ++kb) {
        __syncthreads();
        Hs[lk + 0][lr] = ph.x;  Hs[lk + 1][lr] = ph.y;
        Hs[lk + 2][lr] = ph.z;  Hs[lk + 3][lr] = ph.w;
        Ws2[lk + 0][lr] = pw0.x; Ws2[lk + 1][lr] = pw0.y;
        Ws2[lk + 2][lr] = pw0.z; Ws2[lk + 3][lr] = pw0.w;
        Ws2[lk + 0][lr + 64] = pw1.x; Ws2[lk + 1][lr + 64] = pw1.y;
        Ws2[lk + 2][lr + 64] = pw1.z; Ws2[lk + 3][lr + 64] = pw1.w;
        __syncthreads();

        if (kb < 7) {
            const int kn = (kb + 1) << 4;
            ph  = *(const float4*)(H1 + hOff + kn);
            pw0 = *(const float4*)(Wout + wOff0 + kn);
            pw1 = *(const float4*)(Wout + wOff1 + kn);
        }

#pragma unroll
        for (int kk = 0; kk < 16; ++kk) {
            float4 a0 = *(const float4*)&Hs[kk][ty << 3];
            float4 a1 = *(const float4*)&Hs[kk][(ty << 3) + 4];
            ull b0 = *(const ull*)&Ws2[kk][(tx << 2) + 0];
            ull b1 = *(const ull*)&Ws2[kk][(tx << 2) + 2];
            float av[8] = {a0.x, a0.y, a0.z, a0.w, a1.x, a1.y, a1.z, a1.w};
#pragma unroll
            for (int r = 0; r < 8; ++r) {
                ull ad = dup2(av[r]);
                ffma2(acc[r][0], ad, b0);
                ffma2(acc[r][1], ad, b1);
            }
        }
    }

    float* pp = g_pp + (size_t)ks * (Bsz * INd);
#pragma unroll
    for (int r = 0; r < 8; ++r) {
        const int b = bBase + (ty << 3) + r;
        float v0, v1, v2, v3;
        unpk(acc[r][0], v0, v1);
        unpk(acc[r][1], v2, v3);
        float* p = pp + (size_t)b * INd + (tx << 2);
        p[0] = v0; p[1] = v1; p[2] = v2; p[3] = v3;
    }
}

// reduce partials, add base + b_out; update g_xlast and write out[:, spos, :]
__global__ void __launch_bounds__(256, 1)
proj_reduce_kernel(const float* __restrict__ bout,
                   const float* __restrict__ base, int ldb,
                   float* __restrict__ out, int spos)
{
    int idx = blockIdx.x * 256 + threadIdx.x;   // < 512*128
    int b = idx >> 7, i = idx & 127;
    float s = 0.f;
#pragma unroll
    for (int k = 0; k < 8; ++k) s += g_pp[k * (Bsz * INd) + idx];
    float bv = base ? base[(size_t)b * ldb + i] : g_xlast[idx];
    float v = bv + s + bout[i];
    g_xlast[idx] = v;
    out[(size_t)b * OUTROW + spos * INd + i] = v;
}

// --------------------------------- driver -----------------------------------
extern "C" void kernel_launch(void* const* d_in, const int* in_sizes, int n_in,
                              void* d_out, int out_size)
{
    const float* x     = (const float*)d_in[0];
    const float* W_ih0 = (const float*)d_in[1];
    const float* W_hh0 = (const float*)d_in[2];
    const float* b_ih0 = (const float*)d_in[3];
    const float* b_hh0 = (const float*)d_in[4];
    const float* W_ih1 = (const float*)d_in[5];
    const float* W_hh1 = (const float*)d_in[6];
    const float* b_ih1 = (const float*)d_in[7];
    const float* b_hh1 = (const float*)d_in[8];
    const float* W_out = (const float*)d_in[9];
    const float* b_out = (const float*)d_in[10];
    float* out = (float*)d_out;

    zero_state_kernel<<<(Bsz * Hh) / 256, 256>>>();
    copy_prompt_kernel<<<(Bsz * 16 * INd) / 256, 256>>>(x, out);

    dim3 cellGrid(Hh / 32, Bsz / 128);   // 32 x 4 = 128 CTAs
    dim3 projGrid(8, Bsz / 64);          // 8 K-splits x 8 b-tiles

    for (int s = 0; s < 79; ++s) {
        int rd = s & 1, wr = rd ^ 1;
        if (s < 16)
            lstm_cell_kernel<<<cellGrid, 256>>>(x + (size_t)s * INd, 16 * INd, INd,
                                                W_ih0, W_hh0, b_ih0, b_hh0,
                                                0, rd, wr, 0);
        else
            lstm_cell_kernel<<<cellGrid, 256>>>(nullptr, INd, INd,
                                                W_ih0, W_hh0, b_ih0, b_hh0,
                                                0, rd, wr, 1);
        lstm_cell_kernel<<<cellGrid, 256>>>(nullptr, Hh, Hh,
                                            W_ih1, W_hh1, b_ih1, b_hh1,
                                            1, rd, wr, 2);
        if (s >= 15) {
            proj_part_kernel<<<projGrid, 256>>>(W_out, wr);
            if (s == 15)
                proj_reduce_kernel<<<(Bsz * INd) / 256, 256>>>(
                    b_out, x + 15 * INd, 16 * INd, out, 16);
            else
                proj_reduce_kernel<<<(Bsz * INd) / 256, 256>>>(
                    b_out, nullptr, INd, out, s + 1);
        }
    }
}